// round 1
// baseline (speedup 1.0000x reference)
#include <cuda_runtime.h>
#include <math.h>

#define SEQ_LEN 12
#define HD   128
#define EMB  64
#define KTOT 192           // EMB + HD
#define NJ   512           // 4*HD gate columns
#define MT   64            // pedestrians per block
#define NTH  512
#define ROWP 68            // padded SMEM row (floats), 16B-aligned rows
#define SMEM_BYTES ((KTOT * ROWP + MT * 2) * 4)

// Pre-transposed combined weight, k-major: g_WT[k*512 + j]
__device__ float g_WT[KTOT * NJ];
__device__ float g_bias[NJ];

__global__ void prep_kernel(const float* __restrict__ w_ih,   // [512,64]
                            const float* __restrict__ w_hh,   // [512,128]
                            const float* __restrict__ b_ih,
                            const float* __restrict__ b_hh) {
    int idx = blockIdx.x * blockDim.x + threadIdx.x;
    if (idx < KTOT * NJ) {
        int k = idx / NJ, j = idx % NJ;
        g_WT[idx] = (k < EMB) ? w_ih[j * EMB + k] : w_hh[j * HD + (k - EMB)];
    }
    if (idx < NJ) g_bias[idx] = b_ih[idx] + b_hh[idx];
}

__device__ __forceinline__ float sigm(float x) {
    return 1.0f / (1.0f + expf(-x));
}

__global__ __launch_bounds__(NTH, 1)
void decoder_kernel(const float* __restrict__ lpr,   // last_pos_rel [N,2]
                    const float* __restrict__ h0,    // [N,128]
                    const float* __restrict__ c0,    // [N,128]
                    const float* __restrict__ w_se,  // [64,2]
                    const float* __restrict__ b_se,  // [64]
                    const float* __restrict__ w_hp,  // [2,128]
                    const float* __restrict__ b_hp,  // [2]
                    float* __restrict__ out,         // [12,N,2]
                    int N) {
    extern __shared__ __align__(16) float smem[];
    float (*act_s)[ROWP] = (float (*)[ROWP])smem;          // [192][68]: rows 0..63 dec_in, 64..191 h
    float (*rel_s)[2]    = (float (*)[2])(smem + KTOT * ROWP);

    const int tid  = threadIdx.x;
    const int wid  = tid >> 5;
    const int lane = tid & 31;
    const int u    = (wid & 3) * 32 + lane;   // hidden unit 0..127 (coalesced weight lanes)
    const int m0   = (wid >> 2) * 16;         // ped sub-group base 0/16/32/48
    const int pbase = blockIdx.x * MT;

    // ---- prologue: h0 into act_s rows 64..191 (coalesced gmem reads) ----
    for (int i = tid; i < MT * HD; i += NTH) {
        int ml = i >> 7;        // ped local
        int uu = i & 127;
        act_s[EMB + uu][ml] = h0[(size_t)(pbase + ml) * HD + uu];
    }
    // ---- dec_in0 = last_pos_rel @ w_se^T + b_se ----
    for (int i = tid; i < MT * EMB; i += NTH) {
        int ml = i >> 6;
        int e  = i & 63;
        float r0 = lpr[(size_t)(pbase + ml) * 2 + 0];
        float r1 = lpr[(size_t)(pbase + ml) * 2 + 1];
        act_s[e][ml] = fmaf(r0, w_se[e * 2 + 0], fmaf(r1, w_se[e * 2 + 1], b_se[e]));
    }
    // ---- cell state in registers: c[(pbase+m0+m)][u] ----
    float creg[16];
    #pragma unroll
    for (int m = 0; m < 16; m++)
        creg[m] = c0[(size_t)(pbase + m0 + m) * HD + u];

    const float bi = g_bias[u];
    const float bf = g_bias[HD + u];
    const float bg = g_bias[2 * HD + u];
    const float bo = g_bias[3 * HD + u];

    __syncthreads();

    for (int t = 0; t < SEQ_LEN; t++) {
        // ---- main GEMM: gates[m][{i,f,g,o}*128+u] over K=192 ----
        float ai[16], af[16], ag[16], ao[16];
        #pragma unroll
        for (int m = 0; m < 16; m++) { ai[m] = bi; af[m] = bf; ag[m] = bg; ao[m] = bo; }

        const float* wt = g_WT + u;
        #pragma unroll 4
        for (int k = 0; k < KTOT; k++) {
            float w0 = wt[(size_t)k * NJ];
            float w1 = wt[(size_t)k * NJ + HD];
            float w2 = wt[(size_t)k * NJ + 2 * HD];
            float w3 = wt[(size_t)k * NJ + 3 * HD];
            #pragma unroll
            for (int m = 0; m < 16; m++) {
                float a = act_s[k][m0 + m];   // warp-uniform -> SMEM broadcast
                ai[m] = fmaf(w0, a, ai[m]);
                af[m] = fmaf(w1, a, af[m]);
                ag[m] = fmaf(w2, a, ag[m]);
                ao[m] = fmaf(w3, a, ao[m]);
            }
        }
        __syncthreads();   // everyone done reading old h

        // ---- LSTM cell update; write new h into act_s ----
        #pragma unroll
        for (int m = 0; m < 16; m++) {
            float ig = sigm(ai[m]);
            float fg = sigm(af[m]);
            float og = sigm(ao[m]);
            float gg = tanhf(ag[m]);
            float c  = fmaf(fg, creg[m], ig * gg);
            creg[m]  = c;
            act_s[EMB + u][m0 + m] = og * tanhf(c);
        }
        __syncthreads();   // new h visible

        // ---- rel = h @ w_hp^T + b_hp ; write output ----
        if (tid < 2 * MT) {
            int d  = tid & 1;
            int ml = tid >> 1;
            float r = b_hp[d];
            const float* wh = w_hp + d * HD;
            #pragma unroll 8
            for (int uu = 0; uu < HD; uu++)
                r = fmaf(act_s[EMB + uu][ml], wh[uu], r);
            rel_s[ml][d] = r;
            out[(size_t)t * N * 2 + (size_t)(pbase + ml) * 2 + d] = r;
        }
        __syncthreads();

        // ---- next dec_in = rel @ w_se^T + b_se ----
        if (t < SEQ_LEN - 1) {
            for (int i = tid; i < MT * EMB; i += NTH) {
                int ml = i >> 6;
                int e  = i & 63;
                act_s[e][ml] = fmaf(rel_s[ml][0], w_se[e * 2 + 0],
                                fmaf(rel_s[ml][1], w_se[e * 2 + 1], b_se[e]));
            }
        }
        __syncthreads();
    }
}

extern "C" void kernel_launch(void* const* d_in, const int* in_sizes, int n_in,
                              void* d_out, int out_size) {
    // metadata order: last_pos, last_pos_rel, h0, c0, w_ih, w_hh, b_ih, b_hh,
    //                 w_se, b_se, w_hp, b_hp    (last_pos never affects rels)
    const float* last_pos_rel = (const float*)d_in[1];
    const float* h0   = (const float*)d_in[2];
    const float* c0   = (const float*)d_in[3];
    const float* w_ih = (const float*)d_in[4];
    const float* w_hh = (const float*)d_in[5];
    const float* b_ih = (const float*)d_in[6];
    const float* b_hh = (const float*)d_in[7];
    const float* w_se = (const float*)d_in[8];
    const float* b_se = (const float*)d_in[9];
    const float* w_hp = (const float*)d_in[10];
    const float* b_hp = (const float*)d_in[11];
    float* out = (float*)d_out;

    int N = in_sizes[0] / 2;   // 65536

    cudaFuncSetAttribute(decoder_kernel,
                         cudaFuncAttributeMaxDynamicSharedMemorySize, SMEM_BYTES);

    prep_kernel<<<(KTOT * NJ + 255) / 256, 256>>>(w_ih, w_hh, b_ih, b_hh);
    decoder_kernel<<<N / MT, NTH, SMEM_BYTES>>>(
        last_pos_rel, h0, c0, w_se, b_se, w_hp, b_hp, out, N);
}